// round 4
// baseline (speedup 1.0000x reference)
#include <cuda_runtime.h>
#include <math.h>
#include <stdint.h>

#define H 768
#define HEADS 8
#define HH 6144          // HEADS*H
#define T_STEPS 3
#define BATCH 128
#define NN 6272          // total nodes
#define EE 18432         // total edges
#define G3 2304          // 3*H

// ---------------- scratch (device globals; no allocation allowed) ----------
__device__ float g_h[NN * H];
__device__ float g_fs[(size_t)NN * HH];
__device__ float g_fd[(size_t)NN * HH];
__device__ float g_logits[EE * HEADS];
__device__ float g_a[EE * HEADS];
__device__ float g_x[BATCH * H];
__device__ float g_gi[BATCH * G3];
__device__ float g_gh[BATCH * G3];
__device__ float g_mol[BATCH * H];
__device__ int   g_indeg[NN];
__device__ int   g_off[NN + 1];
__device__ int   g_cur[NN];
__device__ int   g_csr[EE];

// ---------------- tiny utility kernels -------------------------------------
__global__ void copy_h_kernel(const float* __restrict__ in) {
    for (int i = blockIdx.x * blockDim.x + threadIdx.x; i < NN * H; i += gridDim.x * blockDim.x)
        g_h[i] = in[i];
}
__global__ void copy_mol_kernel(const float* __restrict__ in) {
    int i = blockIdx.x * blockDim.x + threadIdx.x;
    if (i < BATCH * H) g_mol[i] = in[i];
}
__global__ void write_mol_out_kernel(float* __restrict__ out) {
    int i = blockIdx.x * blockDim.x + threadIdx.x;
    if (i < BATCH * H) out[i] = g_mol[i];
}

// ---------------- CSR build -------------------------------------------------
__global__ void zero_indeg_kernel() {
    int i = blockIdx.x * blockDim.x + threadIdx.x;
    if (i < NN) g_indeg[i] = 0;
}
__global__ void count_indeg_kernel(const int* __restrict__ dst) {
    int e = blockIdx.x * blockDim.x + threadIdx.x;
    if (e < EE) atomicAdd(&g_indeg[dst[e]], 1);
}
__global__ void scan_kernel() {
    __shared__ int partial[1024];
    const int tid = threadIdx.x;
    const int per = (NN + 1023) / 1024;   // 7
    int base = tid * per;
    int s = 0;
    for (int i = 0; i < per; i++) {
        int idx = base + i;
        if (idx < NN) s += g_indeg[idx];
    }
    partial[tid] = s;
    __syncthreads();
    for (int off = 1; off < 1024; off <<= 1) {
        int v = (tid >= off) ? partial[tid - off] : 0;
        __syncthreads();
        partial[tid] += v;
        __syncthreads();
    }
    int run = (tid > 0) ? partial[tid - 1] : 0;   // exclusive base
    for (int i = 0; i < per; i++) {
        int idx = base + i;
        if (idx < NN) { g_off[idx] = run; run += g_indeg[idx]; }
    }
    if (tid == 1023) g_off[NN] = partial[1023];
}
__global__ void init_cursor_kernel() {
    int i = blockIdx.x * blockDim.x + threadIdx.x;
    if (i < NN) g_cur[i] = g_off[i];
}
__global__ void scatter_kernel(const int* __restrict__ dst) {
    int e = blockIdx.x * blockDim.x + threadIdx.x;
    if (e < EE) {
        int p = atomicAdd(&g_cur[dst[e]], 1);
        g_csr[p] = e;
    }
}
// deterministic edge order per node (sum order stable across replays)
__global__ void sort_csr_kernel() {
    int n = blockIdx.x * blockDim.x + threadIdx.x;
    if (n >= NN) return;
    int s0 = g_off[n], s1 = g_off[n + 1];
    for (int i = s0 + 1; i < s1; i++) {
        int v = g_csr[i];
        int j = i - 1;
        while (j >= s0 && g_csr[j] > v) { g_csr[j + 1] = g_csr[j]; j--; }
        g_csr[j + 1] = v;
    }
}

// ---------------- TF32 helpers ----------------------------------------------
__device__ __forceinline__ float tf32r(float x) {
    uint32_t r;
    asm("cvt.rna.tf32.f32 %0, %1;" : "=r"(r) : "f"(x));
    return __uint_as_float(r);
}
__device__ __forceinline__ void mma_tf32(float c[4],
    uint32_t a0, uint32_t a1, uint32_t a2, uint32_t a3,
    uint32_t b0, uint32_t b1)
{
    asm volatile(
        "mma.sync.aligned.m16n8k8.row.col.f32.tf32.tf32.f32 "
        "{%0,%1,%2,%3}, {%4,%5,%6,%7}, {%8,%9}, {%0,%1,%2,%3};\n"
        : "+f"(c[0]), "+f"(c[1]), "+f"(c[2]), "+f"(c[3])
        : "r"(a0), "r"(a1), "r"(a2), "r"(a3), "r"(b0), "r"(b1));
}

// ---------------- big GEMM (TF32 tensor cores) ------------------------------
// C[M,Nn] = A[M,K] @ B[K,Nn] + bias[Nn].  M=6272, Nn=6144, K=768.
// 128x128 tile, 256 threads = 8 warps in 2(M)x4(N); each warp 64x32 via
// 4x4 tiles of mma.m16n8k8. Double-buffered smem, tf32-rounded staging.
__global__ __launch_bounds__(256, 2) void sgemm128(
    const float* __restrict__ A, const float* __restrict__ Bm,
    const float* __restrict__ bias, float* __restrict__ C,
    int M, int Nn, int K)
{
    __shared__ float As[2][8][128];   // As[buf][k][m]
    __shared__ float Bs[2][8][128];   // Bs[buf][k][n]
    const int bM = blockIdx.y * 128, bN = blockIdx.x * 128;
    const int tid = threadIdx.x;
    const int aRow = tid >> 1, aK = (tid & 1) * 4;
    const int bRow = tid >> 5, bCol = (tid & 31) * 4;

    const int lane = tid & 31, w = tid >> 5;
    const int wm = (w & 1) * 64;       // warp M offset in tile
    const int wn = (w >> 1) * 32;      // warp N offset in tile
    const int gID = lane >> 2, tig = lane & 3;

    float acc[4][4][4];
#pragma unroll
    for (int mi = 0; mi < 4; mi++)
#pragma unroll
        for (int nj = 0; nj < 4; nj++)
#pragma unroll
            for (int r = 0; r < 4; r++) acc[mi][nj][r] = 0.f;

    // preload k-tile 0 into buffer 0 (tf32-rounded)
    {
        float4 av = *(const float4*)(A + (size_t)(bM + aRow) * K + aK);
        float4 bv = *(const float4*)(Bm + (size_t)bRow * Nn + bN + bCol);
        As[0][aK + 0][aRow] = tf32r(av.x);
        As[0][aK + 1][aRow] = tf32r(av.y);
        As[0][aK + 2][aRow] = tf32r(av.z);
        As[0][aK + 3][aRow] = tf32r(av.w);
        float4 bt = make_float4(tf32r(bv.x), tf32r(bv.y), tf32r(bv.z), tf32r(bv.w));
        *(float4*)&Bs[0][bRow][bCol] = bt;
    }
    __syncthreads();

    int p = 0;
    for (int k0 = 0; k0 < K; k0 += 8) {
        if (k0 + 8 < K) {   // prefetch next tile into the other buffer
            float4 av = *(const float4*)(A + (size_t)(bM + aRow) * K + (k0 + 8) + aK);
            float4 bv = *(const float4*)(Bm + (size_t)(k0 + 8 + bRow) * Nn + bN + bCol);
            As[p ^ 1][aK + 0][aRow] = tf32r(av.x);
            As[p ^ 1][aK + 1][aRow] = tf32r(av.y);
            As[p ^ 1][aK + 2][aRow] = tf32r(av.z);
            As[p ^ 1][aK + 3][aRow] = tf32r(av.w);
            float4 bt = make_float4(tf32r(bv.x), tf32r(bv.y), tf32r(bv.z), tf32r(bv.w));
            *(float4*)&Bs[p ^ 1][bRow][bCol] = bt;
        }

        // A fragments: rows wm+mi*16+gID(+8), k cols tig(+4)
        uint32_t af[4][4];
#pragma unroll
        for (int mi = 0; mi < 4; mi++) {
            int r0 = wm + mi * 16 + gID;
            af[mi][0] = __float_as_uint(As[p][tig]    [r0]);
            af[mi][1] = __float_as_uint(As[p][tig]    [r0 + 8]);
            af[mi][2] = __float_as_uint(As[p][tig + 4][r0]);
            af[mi][3] = __float_as_uint(As[p][tig + 4][r0 + 8]);
        }
        // B fragments: k rows tig(+4), n col wn+nj*8+gID
        uint32_t bf[4][2];
#pragma unroll
        for (int nj = 0; nj < 4; nj++) {
            int c0 = wn + nj * 8 + gID;
            bf[nj][0] = __float_as_uint(Bs[p][tig]    [c0]);
            bf[nj][1] = __float_as_uint(Bs[p][tig + 4][c0]);
        }
#pragma unroll
        for (int mi = 0; mi < 4; mi++)
#pragma unroll
            for (int nj = 0; nj < 4; nj++)
                mma_tf32(acc[mi][nj], af[mi][0], af[mi][1], af[mi][2], af[mi][3],
                         bf[nj][0], bf[nj][1]);

        __syncthreads();
        p ^= 1;
    }

    // epilogue: c0:(gID, 2*tig) c1:(gID, 2*tig+1) c2:(gID+8, 2*tig) c3:(+1)
#pragma unroll
    for (int mi = 0; mi < 4; mi++) {
#pragma unroll
        for (int nj = 0; nj < 4; nj++) {
            int row0 = bM + wm + mi * 16 + gID;
            int col  = bN + wn + nj * 8 + 2 * tig;
            float b0 = bias[col], b1 = bias[col + 1];
            float2 v0 = make_float2(acc[mi][nj][0] + b0, acc[mi][nj][1] + b1);
            float2 v1 = make_float2(acc[mi][nj][2] + b0, acc[mi][nj][3] + b1);
            *(float2*)(C + (size_t)row0 * Nn + col)       = v0;
            *(float2*)(C + (size_t)(row0 + 8) * Nn + col) = v1;
        }
    }
}

// ---------------- edge logits: leaky_relu(fs[src]+fd[dst]) . a --------------
__global__ __launch_bounds__(256) void edge_logits_kernel(
    const int* __restrict__ src, const int* __restrict__ dst,
    const float* __restrict__ attn_a_t)
{
    int e = blockIdx.x;
    int w = threadIdx.x >> 5, lane = threadIdx.x & 31;
    const float* fsrow = g_fs + (size_t)src[e] * HH + w * H;
    const float* fdrow = g_fd + (size_t)dst[e] * HH + w * H;
    const float* arow  = attn_a_t + w * H;
    float acc = 0.f;
    for (int i = lane * 4; i < H; i += 128) {
        float4 s4 = *(const float4*)(fsrow + i);
        float4 d4 = *(const float4*)(fdrow + i);
        float4 a4 = *(const float4*)(arow + i);
        float v;
        v = s4.x + d4.x; v = (v > 0.f) ? v : 0.2f * v; acc += v * a4.x;
        v = s4.y + d4.y; v = (v > 0.f) ? v : 0.2f * v; acc += v * a4.y;
        v = s4.z + d4.z; v = (v > 0.f) ? v : 0.2f * v; acc += v * a4.z;
        v = s4.w + d4.w; v = (v > 0.f) ? v : 0.2f * v; acc += v * a4.w;
    }
#pragma unroll
    for (int o = 16; o > 0; o >>= 1) acc += __shfl_xor_sync(0xFFFFFFFFu, acc, o);
    if (lane == 0) g_logits[e * HEADS + w] = acc;
}

// ---------------- edge softmax per (dst node, head) -------------------------
__global__ void edge_softmax_kernel() {
    int t = blockIdx.x * blockDim.x + threadIdx.x;
    if (t >= NN * HEADS) return;
    int n = t / HEADS, hh = t % HEADS;
    int s0 = g_off[n], s1 = g_off[n + 1];
    if (s0 == s1) return;
    float m = -INFINITY;
    for (int i = s0; i < s1; i++)
        m = fmaxf(m, g_logits[g_csr[i] * HEADS + hh]);
    float sum = 0.f;
    for (int i = s0; i < s1; i++) {
        int eid = g_csr[i];
        float ex = expf(g_logits[eid * HEADS + hh] - m);
        g_a[eid * HEADS + hh] = ex;
        sum += ex;
    }
    float inv = 1.f / sum;
    for (int i = s0; i < s1; i++)
        g_a[g_csr[i] * HEADS + hh] *= inv;
}

// ---------------- aggregation: h[n,d] = mean_h sum_e a*fs[src] --------------
__global__ __launch_bounds__(256) void aggregate_kernel(const int* __restrict__ src) {
    int n = blockIdx.x;
    int s0 = g_off[n], s1 = g_off[n + 1];
    const int d0 = threadIdx.x, d1 = d0 + 256, d2 = d1 + 256;
    float a0 = 0.f, a1 = 0.f, a2 = 0.f;
    __shared__ int   ssrc[48];
    __shared__ float sa[48 * 8];
    for (int base = s0; base < s1; base += 48) {
        int cnt = min(48, s1 - base);
        if (threadIdx.x < cnt) {
            int eid = g_csr[base + threadIdx.x];
            ssrc[threadIdx.x] = src[eid];
#pragma unroll
            for (int hh = 0; hh < 8; hh++)
                sa[threadIdx.x * 8 + hh] = g_a[eid * HEADS + hh];
        }
        __syncthreads();
        for (int i = 0; i < cnt; i++) {
            const float* fr = g_fs + (size_t)ssrc[i] * HH;
#pragma unroll
            for (int hh = 0; hh < 8; hh++) {
                float av = sa[i * 8 + hh];
                const float* f = fr + hh * H;
                a0 += av * f[d0];
                a1 += av * f[d1];
                a2 += av * f[d2];
            }
        }
        __syncthreads();
    }
    g_h[n * H + d0] = a0 * 0.125f;
    g_h[n * H + d1] = a1 * 0.125f;
    g_h[n * H + d2] = a2 * 0.125f;
}

// ---------------- GRU pieces ------------------------------------------------
__global__ void gather_virtual_kernel(const int* __restrict__ vnids) {
    int t = blockIdx.x * blockDim.x + threadIdx.x;
    if (t >= BATCH * H) return;
    int b = t / H, j = t % H;
    g_x[t] = g_h[vnids[b] * H + j];
}
// C[m,n] = sum_k A[m,k]*B[n,k] + bias[n]  (NT gemm; M=128, Nn=2304, K=768)
__global__ void gemm_nt16(const float* __restrict__ A, const float* __restrict__ Bm,
                          const float* __restrict__ bias, float* __restrict__ C,
                          int M, int Nn, int K)
{
    __shared__ float As[16][17], Bs[16][17];
    int n = blockIdx.x * 16 + threadIdx.x;
    int m = blockIdx.y * 16 + threadIdx.y;
    float acc = 0.f;
    for (int k0 = 0; k0 < K; k0 += 16) {
        As[threadIdx.y][threadIdx.x] = A[(size_t)m * K + k0 + threadIdx.x];
        Bs[threadIdx.y][threadIdx.x] = Bm[(size_t)(blockIdx.x * 16 + threadIdx.y) * K + k0 + threadIdx.x];
        __syncthreads();
#pragma unroll
        for (int k = 0; k < 16; k++) acc += As[threadIdx.y][k] * Bs[threadIdx.x][k];
        __syncthreads();
    }
    C[(size_t)m * Nn + n] = acc + bias[n];
}
__global__ void gru_gate_kernel() {
    int t = blockIdx.x * blockDim.x + threadIdx.x;
    if (t >= BATCH * H) return;
    int b = t / H, j = t % H;
    float ir = g_gi[b * G3 + j],          hr = g_gh[b * G3 + j];
    float iz = g_gi[b * G3 + H + j],      hz = g_gh[b * G3 + H + j];
    float in_ = g_gi[b * G3 + 2 * H + j], hn = g_gh[b * G3 + 2 * H + j];
    float r = 1.f / (1.f + expf(-(ir + hr)));
    float z = 1.f / (1.f + expf(-(iz + hz)));
    float nv = tanhf(in_ + r * hn);
    float hp = g_mol[t];
    float o = (1.f - z) * nv + z * hp;
    g_mol[t] = fmaxf(o, 0.f);
}

// ---------------- attention output -----------------------------------------
__global__ void attn_out_kernel(const int* __restrict__ attn_eids,
                                float* __restrict__ out, int t) {
    int i = blockIdx.x * blockDim.x + threadIdx.x;
    if (i >= BATCH * 48) return;
    int e = attn_eids[i];
    float s = 0.f;
#pragma unroll
    for (int hh = 0; hh < 8; hh++) s += g_a[e * HEADS + hh];
    out[BATCH * H + t * (BATCH * 48) + i] = s * 0.125f;
}

// ---------------- launch ----------------------------------------------------
extern "C" void kernel_launch(void* const* d_in, const int* in_sizes, int n_in,
                              void* d_out, int out_size)
{
    const float* h_nodes   = (const float*)d_in[0];
    const float* mol_feat  = (const float*)d_in[1];
    const float* W_src     = (const float*)d_in[2];
    const float* b_src     = (const float*)d_in[3];
    const float* W_dst     = (const float*)d_in[4];
    const float* b_dst     = (const float*)d_in[5];
    const float* attn_a    = (const float*)d_in[6];
    const float* W_ih      = (const float*)d_in[7];
    const float* W_hh      = (const float*)d_in[8];
    const float* b_ih      = (const float*)d_in[9];
    const float* b_hh      = (const float*)d_in[10];
    const int*   src       = (const int*)d_in[11];
    const int*   dst       = (const int*)d_in[12];
    const int*   vnids     = (const int*)d_in[13];
    const int*   attn_eids = (const int*)d_in[14];
    float* out = (float*)d_out;

    float* pfs;  cudaGetSymbolAddress((void**)&pfs,  g_fs);
    float* pfd;  cudaGetSymbolAddress((void**)&pfd,  g_fd);
    float* ph;   cudaGetSymbolAddress((void**)&ph,   g_h);
    float* px;   cudaGetSymbolAddress((void**)&px,   g_x);
    float* pgi;  cudaGetSymbolAddress((void**)&pgi,  g_gi);
    float* pgh;  cudaGetSymbolAddress((void**)&pgh,  g_gh);
    float* pmol; cudaGetSymbolAddress((void**)&pmol, g_mol);

    // init state
    copy_h_kernel<<<2048, 256>>>(h_nodes);
    copy_mol_kernel<<<(BATCH * H + 255) / 256, 256>>>(mol_feat);

    // CSR (static structure, rebuilt per launch; deterministic after sort)
    zero_indeg_kernel<<<(NN + 255) / 256, 256>>>();
    count_indeg_kernel<<<(EE + 255) / 256, 256>>>(dst);
    scan_kernel<<<1, 1024>>>();
    init_cursor_kernel<<<(NN + 255) / 256, 256>>>();
    scatter_kernel<<<(EE + 255) / 256, 256>>>(dst);
    sort_csr_kernel<<<(NN + 255) / 256, 256>>>();

    dim3 gemmGrid(HH / 128, NN / 128);   // 48 x 49
    for (int t = 0; t < T_STEPS; t++) {
        const float* Wst = W_src + (size_t)t * H * HH;
        const float* Wdt = W_dst + (size_t)t * H * HH;
        const float* bst = b_src + (size_t)t * HH;
        const float* bdt = b_dst + (size_t)t * HH;
        const float* at  = attn_a + (size_t)t * HEADS * H;
        const float* Wiht = W_ih + (size_t)t * G3 * H;
        const float* Whht = W_hh + (size_t)t * G3 * H;
        const float* biht = b_ih + (size_t)t * G3;
        const float* bhht = b_hh + (size_t)t * G3;

        sgemm128<<<gemmGrid, 256>>>(ph, Wst, bst, pfs, NN, HH, H);
        sgemm128<<<gemmGrid, 256>>>(ph, Wdt, bdt, pfd, NN, HH, H);
        edge_logits_kernel<<<EE, 256>>>(src, dst, at);
        edge_softmax_kernel<<<(NN * HEADS + 255) / 256, 256>>>();
        aggregate_kernel<<<NN, 256>>>(src);
        gather_virtual_kernel<<<(BATCH * H + 255) / 256, 256>>>(vnids);
        gemm_nt16<<<dim3(G3 / 16, BATCH / 16), dim3(16, 16)>>>(px,   Wiht, biht, pgi, BATCH, G3, H);
        gemm_nt16<<<dim3(G3 / 16, BATCH / 16), dim3(16, 16)>>>(pmol, Whht, bhht, pgh, BATCH, G3, H);
        gru_gate_kernel<<<(BATCH * H + 255) / 256, 256>>>();
        attn_out_kernel<<<(BATCH * 48 + 255) / 256, 256>>>(attn_eids, out, t);
    }
    write_mol_out_kernel<<<(BATCH * H + 255) / 256, 256>>>(out);
}

// round 5
// speedup vs baseline: 1.4961x; 1.4961x over previous
#include <cuda_runtime.h>
#include <math.h>
#include <stdint.h>

#define H 768
#define HEADS 8
#define HH 6144          // HEADS*H
#define T_STEPS 3
#define BATCH 128
#define NN 6272          // total nodes
#define EE 18432         // total edges
#define G3 2304          // 3*H

#define SPAD 136         // padded smem row stride (kills LDS bank conflicts)

// ---------------- scratch (device globals; no allocation allowed) ----------
__device__ float g_h[NN * H];
__device__ float g_fs[(size_t)NN * HH];
__device__ float g_fd[(size_t)NN * HH];
__device__ float g_logits[EE * HEADS];
__device__ float g_a[EE * HEADS];
__device__ float g_x[BATCH * H];
__device__ float g_gi[BATCH * G3];
__device__ float g_gh[BATCH * G3];
__device__ float g_mol[BATCH * H];
__device__ int   g_indeg[NN];
__device__ int   g_off[NN + 1];
__device__ int   g_cur[NN];
__device__ int   g_csr[EE];

// ---------------- tiny utility kernels -------------------------------------
__global__ void copy_h_kernel(const float* __restrict__ in) {
    for (int i = blockIdx.x * blockDim.x + threadIdx.x; i < NN * H; i += gridDim.x * blockDim.x)
        g_h[i] = in[i];
}
__global__ void copy_mol_kernel(const float* __restrict__ in) {
    int i = blockIdx.x * blockDim.x + threadIdx.x;
    if (i < BATCH * H) g_mol[i] = in[i];
}
__global__ void write_mol_out_kernel(float* __restrict__ out) {
    int i = blockIdx.x * blockDim.x + threadIdx.x;
    if (i < BATCH * H) out[i] = g_mol[i];
}

// ---------------- CSR build -------------------------------------------------
__global__ void zero_indeg_kernel() {
    int i = blockIdx.x * blockDim.x + threadIdx.x;
    if (i < NN) g_indeg[i] = 0;
}
__global__ void count_indeg_kernel(const int* __restrict__ dst) {
    int e = blockIdx.x * blockDim.x + threadIdx.x;
    if (e < EE) atomicAdd(&g_indeg[dst[e]], 1);
}
__global__ void scan_kernel() {
    __shared__ int partial[1024];
    const int tid = threadIdx.x;
    const int per = (NN + 1023) / 1024;   // 7
    int base = tid * per;
    int s = 0;
    for (int i = 0; i < per; i++) {
        int idx = base + i;
        if (idx < NN) s += g_indeg[idx];
    }
    partial[tid] = s;
    __syncthreads();
    for (int off = 1; off < 1024; off <<= 1) {
        int v = (tid >= off) ? partial[tid - off] : 0;
        __syncthreads();
        partial[tid] += v;
        __syncthreads();
    }
    int run = (tid > 0) ? partial[tid - 1] : 0;   // exclusive base
    for (int i = 0; i < per; i++) {
        int idx = base + i;
        if (idx < NN) { g_off[idx] = run; run += g_indeg[idx]; }
    }
    if (tid == 1023) g_off[NN] = partial[1023];
}
__global__ void init_cursor_kernel() {
    int i = blockIdx.x * blockDim.x + threadIdx.x;
    if (i < NN) g_cur[i] = g_off[i];
}
__global__ void scatter_kernel(const int* __restrict__ dst) {
    int e = blockIdx.x * blockDim.x + threadIdx.x;
    if (e < EE) {
        int p = atomicAdd(&g_cur[dst[e]], 1);
        g_csr[p] = e;
    }
}
// deterministic edge order per node (sum order stable across replays)
__global__ void sort_csr_kernel() {
    int n = blockIdx.x * blockDim.x + threadIdx.x;
    if (n >= NN) return;
    int s0 = g_off[n], s1 = g_off[n + 1];
    for (int i = s0 + 1; i < s1; i++) {
        int v = g_csr[i];
        int j = i - 1;
        while (j >= s0 && g_csr[j] > v) { g_csr[j + 1] = g_csr[j]; j--; }
        g_csr[j + 1] = v;
    }
}

// ---------------- TF32 helpers ----------------------------------------------
__device__ __forceinline__ float tf32r(float x) {
    uint32_t r;
    asm("cvt.rna.tf32.f32 %0, %1;" : "=r"(r) : "f"(x));
    return __uint_as_float(r);
}
__device__ __forceinline__ void mma_tf32(float c[4],
    uint32_t a0, uint32_t a1, uint32_t a2, uint32_t a3,
    uint32_t b0, uint32_t b1)
{
    asm volatile(
        "mma.sync.aligned.m16n8k8.row.col.f32.tf32.tf32.f32 "
        "{%0,%1,%2,%3}, {%4,%5,%6,%7}, {%8,%9}, {%0,%1,%2,%3};\n"
        : "+f"(c[0]), "+f"(c[1]), "+f"(c[2]), "+f"(c[3])
        : "r"(a0), "r"(a1), "r"(a2), "r"(a3), "r"(b0), "r"(b1));
}

// ---------------- fused dual GEMM (TF32 tensor cores) -----------------------
// z=0: fs = h @ W_src + b_src ; z=1: fd = h @ W_dst + b_dst
// 128x128 tile, K-chunk 16, padded smem (conflict-free fragment LDS),
// 8 warps in 2(M)x4(N), each warp 64x32 via 4x4 m16n8k8 tiles.
__global__ __launch_bounds__(256, 2) void sgemm_dual(
    const float* __restrict__ A,
    const float* __restrict__ Bsrc, const float* __restrict__ bsrc,
    const float* __restrict__ Bdst, const float* __restrict__ bdst,
    float* __restrict__ Cs, float* __restrict__ Cd,
    int M, int Nn, int K)
{
    const float* Bm   = blockIdx.z ? Bdst : Bsrc;
    const float* bias = blockIdx.z ? bdst : bsrc;
    float*       C    = blockIdx.z ? Cd   : Cs;

    __shared__ float As[2][16][SPAD];   // [buf][k][m]
    __shared__ float Bs[2][16][SPAD];   // [buf][k][n]
    const int bM = blockIdx.y * 128, bN = blockIdx.x * 128;
    const int tid = threadIdx.x;

    // A loader: row = tid&127 (consecutive in warp -> conflict-free stores),
    // kbase = (tid>>7)*8; 8 floats per thread.
    const int aRow = tid & 127, aKb = (tid >> 7) * 8;
    // B loader: rows bRow and bRow+8, one float4 each.
    const int bRow = tid >> 5, bCol = (tid & 31) * 4;

    const int lane = tid & 31, w = tid >> 5;
    const int wm = (w & 1) * 64;       // warp M offset in tile
    const int wn = (w >> 1) * 32;      // warp N offset in tile
    const int gID = lane >> 2, tig = lane & 3;

    float acc[4][4][4];
#pragma unroll
    for (int mi = 0; mi < 4; mi++)
#pragma unroll
        for (int nj = 0; nj < 4; nj++)
#pragma unroll
            for (int r = 0; r < 4; r++) acc[mi][nj][r] = 0.f;

    // preload k-tile 0 into buffer 0 (tf32-rounded)
    {
        float4 a0 = *(const float4*)(A + (size_t)(bM + aRow) * K + aKb);
        float4 a1 = *(const float4*)(A + (size_t)(bM + aRow) * K + aKb + 4);
        As[0][aKb + 0][aRow] = tf32r(a0.x);
        As[0][aKb + 1][aRow] = tf32r(a0.y);
        As[0][aKb + 2][aRow] = tf32r(a0.z);
        As[0][aKb + 3][aRow] = tf32r(a0.w);
        As[0][aKb + 4][aRow] = tf32r(a1.x);
        As[0][aKb + 5][aRow] = tf32r(a1.y);
        As[0][aKb + 6][aRow] = tf32r(a1.z);
        As[0][aKb + 7][aRow] = tf32r(a1.w);
        float4 b0 = *(const float4*)(Bm + (size_t)bRow * Nn + bN + bCol);
        float4 b1 = *(const float4*)(Bm + (size_t)(bRow + 8) * Nn + bN + bCol);
        *(float4*)&Bs[0][bRow][bCol] =
            make_float4(tf32r(b0.x), tf32r(b0.y), tf32r(b0.z), tf32r(b0.w));
        *(float4*)&Bs[0][bRow + 8][bCol] =
            make_float4(tf32r(b1.x), tf32r(b1.y), tf32r(b1.z), tf32r(b1.w));
    }
    __syncthreads();

    int p = 0;
    for (int k0 = 0; k0 < K; k0 += 16) {
        if (k0 + 16 < K) {   // prefetch next 16-k tile into other buffer
            const float* Ap = A + (size_t)(bM + aRow) * K + (k0 + 16) + aKb;
            float4 a0 = *(const float4*)(Ap);
            float4 a1 = *(const float4*)(Ap + 4);
            As[p ^ 1][aKb + 0][aRow] = tf32r(a0.x);
            As[p ^ 1][aKb + 1][aRow] = tf32r(a0.y);
            As[p ^ 1][aKb + 2][aRow] = tf32r(a0.z);
            As[p ^ 1][aKb + 3][aRow] = tf32r(a0.w);
            As[p ^ 1][aKb + 4][aRow] = tf32r(a1.x);
            As[p ^ 1][aKb + 5][aRow] = tf32r(a1.y);
            As[p ^ 1][aKb + 6][aRow] = tf32r(a1.z);
            As[p ^ 1][aKb + 7][aRow] = tf32r(a1.w);
            float4 b0 = *(const float4*)(Bm + (size_t)(k0 + 16 + bRow) * Nn + bN + bCol);
            float4 b1 = *(const float4*)(Bm + (size_t)(k0 + 24 + bRow) * Nn + bN + bCol);
            *(float4*)&Bs[p ^ 1][bRow][bCol] =
                make_float4(tf32r(b0.x), tf32r(b0.y), tf32r(b0.z), tf32r(b0.w));
            *(float4*)&Bs[p ^ 1][bRow + 8][bCol] =
                make_float4(tf32r(b1.x), tf32r(b1.y), tf32r(b1.z), tf32r(b1.w));
        }

#pragma unroll
        for (int ks = 0; ks < 16; ks += 8) {
            // A fragments: conflict-free (bank = tig*8 + gID + const)
            uint32_t af[4][4];
#pragma unroll
            for (int mi = 0; mi < 4; mi++) {
                int r0 = wm + mi * 16 + gID;
                af[mi][0] = __float_as_uint(As[p][ks + tig]    [r0]);
                af[mi][1] = __float_as_uint(As[p][ks + tig]    [r0 + 8]);
                af[mi][2] = __float_as_uint(As[p][ks + tig + 4][r0]);
                af[mi][3] = __float_as_uint(As[p][ks + tig + 4][r0 + 8]);
            }
            uint32_t bf[4][2];
#pragma unroll
            for (int nj = 0; nj < 4; nj++) {
                int c0 = wn + nj * 8 + gID;
                bf[nj][0] = __float_as_uint(Bs[p][ks + tig]    [c0]);
                bf[nj][1] = __float_as_uint(Bs[p][ks + tig + 4][c0]);
            }
#pragma unroll
            for (int mi = 0; mi < 4; mi++)
#pragma unroll
                for (int nj = 0; nj < 4; nj++)
                    mma_tf32(acc[mi][nj], af[mi][0], af[mi][1], af[mi][2], af[mi][3],
                             bf[nj][0], bf[nj][1]);
        }

        __syncthreads();
        p ^= 1;
    }

    // epilogue
#pragma unroll
    for (int mi = 0; mi < 4; mi++) {
#pragma unroll
        for (int nj = 0; nj < 4; nj++) {
            int row0 = bM + wm + mi * 16 + gID;
            int col  = bN + wn + nj * 8 + 2 * tig;
            float b0 = bias[col], b1 = bias[col + 1];
            float2 v0 = make_float2(acc[mi][nj][0] + b0, acc[mi][nj][1] + b1);
            float2 v1 = make_float2(acc[mi][nj][2] + b0, acc[mi][nj][3] + b1);
            *(float2*)(C + (size_t)row0 * Nn + col)       = v0;
            *(float2*)(C + (size_t)(row0 + 8) * Nn + col) = v1;
        }
    }
}

// ---------------- edge logits: leaky_relu(fs[src]+fd[dst]) . a --------------
__global__ __launch_bounds__(256) void edge_logits_kernel(
    const int* __restrict__ src, const int* __restrict__ dst,
    const float* __restrict__ attn_a_t)
{
    int e = blockIdx.x;
    int w = threadIdx.x >> 5, lane = threadIdx.x & 31;
    const float* fsrow = g_fs + (size_t)src[e] * HH + w * H;
    const float* fdrow = g_fd + (size_t)dst[e] * HH + w * H;
    const float* arow  = attn_a_t + w * H;
    float acc = 0.f;
    for (int i = lane * 4; i < H; i += 128) {
        float4 s4 = *(const float4*)(fsrow + i);
        float4 d4 = *(const float4*)(fdrow + i);
        float4 a4 = *(const float4*)(arow + i);
        float v;
        v = s4.x + d4.x; v = (v > 0.f) ? v : 0.2f * v; acc += v * a4.x;
        v = s4.y + d4.y; v = (v > 0.f) ? v : 0.2f * v; acc += v * a4.y;
        v = s4.z + d4.z; v = (v > 0.f) ? v : 0.2f * v; acc += v * a4.z;
        v = s4.w + d4.w; v = (v > 0.f) ? v : 0.2f * v; acc += v * a4.w;
    }
#pragma unroll
    for (int o = 16; o > 0; o >>= 1) acc += __shfl_xor_sync(0xFFFFFFFFu, acc, o);
    if (lane == 0) g_logits[e * HEADS + w] = acc;
}

// ---------------- edge softmax per (dst node, head) -------------------------
__global__ void edge_softmax_kernel() {
    int t = blockIdx.x * blockDim.x + threadIdx.x;
    if (t >= NN * HEADS) return;
    int n = t / HEADS, hh = t % HEADS;
    int s0 = g_off[n], s1 = g_off[n + 1];
    if (s0 == s1) return;
    float m = -INFINITY;
    for (int i = s0; i < s1; i++)
        m = fmaxf(m, g_logits[g_csr[i] * HEADS + hh]);
    float sum = 0.f;
    for (int i = s0; i < s1; i++) {
        int eid = g_csr[i];
        float ex = expf(g_logits[eid * HEADS + hh] - m);
        g_a[eid * HEADS + hh] = ex;
        sum += ex;
    }
    float inv = 1.f / sum;
    for (int i = s0; i < s1; i++)
        g_a[g_csr[i] * HEADS + hh] *= inv;
}

// ---------------- aggregation: h[n,d] = mean_h sum_e a*fs[src] --------------
__global__ __launch_bounds__(256) void aggregate_kernel(const int* __restrict__ src) {
    int n = blockIdx.x;
    int s0 = g_off[n], s1 = g_off[n + 1];
    const int d0 = threadIdx.x, d1 = d0 + 256, d2 = d1 + 256;
    float a0 = 0.f, a1 = 0.f, a2 = 0.f;
    __shared__ int   ssrc[48];
    __shared__ float sa[48 * 8];
    for (int base = s0; base < s1; base += 48) {
        int cnt = min(48, s1 - base);
        if (threadIdx.x < cnt) {
            int eid = g_csr[base + threadIdx.x];
            ssrc[threadIdx.x] = src[eid];
#pragma unroll
            for (int hh = 0; hh < 8; hh++)
                sa[threadIdx.x * 8 + hh] = g_a[eid * HEADS + hh];
        }
        __syncthreads();
        for (int i = 0; i < cnt; i++) {
            const float* fr = g_fs + (size_t)ssrc[i] * HH;
#pragma unroll
            for (int hh = 0; hh < 8; hh++) {
                float av = sa[i * 8 + hh];
                const float* f = fr + hh * H;
                a0 += av * f[d0];
                a1 += av * f[d1];
                a2 += av * f[d2];
            }
        }
        __syncthreads();
    }
    g_h[n * H + d0] = a0 * 0.125f;
    g_h[n * H + d1] = a1 * 0.125f;
    g_h[n * H + d2] = a2 * 0.125f;
}

// ---------------- GRU pieces ------------------------------------------------
__global__ void gather_virtual_kernel(const int* __restrict__ vnids) {
    int t = blockIdx.x * blockDim.x + threadIdx.x;
    if (t >= BATCH * H) return;
    int b = t / H, j = t % H;
    g_x[t] = g_h[vnids[b] * H + j];
}
// C[m,n] = sum_k A[m,k]*B[n,k] + bias[n]  (NT gemm; M=128, Nn=2304, K=768)
__global__ void gemm_nt16(const float* __restrict__ A, const float* __restrict__ Bm,
                          const float* __restrict__ bias, float* __restrict__ C,
                          int M, int Nn, int K)
{
    __shared__ float As[16][17], Bs[16][17];
    int n = blockIdx.x * 16 + threadIdx.x;
    int m = blockIdx.y * 16 + threadIdx.y;
    float acc = 0.f;
    for (int k0 = 0; k0 < K; k0 += 16) {
        As[threadIdx.y][threadIdx.x] = A[(size_t)m * K + k0 + threadIdx.x];
        Bs[threadIdx.y][threadIdx.x] = Bm[(size_t)(blockIdx.x * 16 + threadIdx.y) * K + k0 + threadIdx.x];
        __syncthreads();
#pragma unroll
        for (int k = 0; k < 16; k++) acc += As[threadIdx.y][k] * Bs[threadIdx.x][k];
        __syncthreads();
    }
    C[(size_t)m * Nn + n] = acc + bias[n];
}
__global__ void gru_gate_kernel() {
    int t = blockIdx.x * blockDim.x + threadIdx.x;
    if (t >= BATCH * H) return;
    int b = t / H, j = t % H;
    float ir = g_gi[b * G3 + j],          hr = g_gh[b * G3 + j];
    float iz = g_gi[b * G3 + H + j],      hz = g_gh[b * G3 + H + j];
    float in_ = g_gi[b * G3 + 2 * H + j], hn = g_gh[b * G3 + 2 * H + j];
    float r = 1.f / (1.f + expf(-(ir + hr)));
    float z = 1.f / (1.f + expf(-(iz + hz)));
    float nv = tanhf(in_ + r * hn);
    float hp = g_mol[t];
    float o = (1.f - z) * nv + z * hp;
    g_mol[t] = fmaxf(o, 0.f);
}

// ---------------- attention output -----------------------------------------
__global__ void attn_out_kernel(const int* __restrict__ attn_eids,
                                float* __restrict__ out, int t) {
    int i = blockIdx.x * blockDim.x + threadIdx.x;
    if (i >= BATCH * 48) return;
    int e = attn_eids[i];
    float s = 0.f;
#pragma unroll
    for (int hh = 0; hh < 8; hh++) s += g_a[e * HEADS + hh];
    out[BATCH * H + t * (BATCH * 48) + i] = s * 0.125f;
}

// ---------------- launch ----------------------------------------------------
extern "C" void kernel_launch(void* const* d_in, const int* in_sizes, int n_in,
                              void* d_out, int out_size)
{
    const float* h_nodes   = (const float*)d_in[0];
    const float* mol_feat  = (const float*)d_in[1];
    const float* W_src     = (const float*)d_in[2];
    const float* b_src     = (const float*)d_in[3];
    const float* W_dst     = (const float*)d_in[4];
    const float* b_dst     = (const float*)d_in[5];
    const float* attn_a    = (const float*)d_in[6];
    const float* W_ih      = (const float*)d_in[7];
    const float* W_hh      = (const float*)d_in[8];
    const float* b_ih      = (const float*)d_in[9];
    const float* b_hh      = (const float*)d_in[10];
    const int*   src       = (const int*)d_in[11];
    const int*   dst       = (const int*)d_in[12];
    const int*   vnids     = (const int*)d_in[13];
    const int*   attn_eids = (const int*)d_in[14];
    float* out = (float*)d_out;

    float* pfs;  cudaGetSymbolAddress((void**)&pfs,  g_fs);
    float* pfd;  cudaGetSymbolAddress((void**)&pfd,  g_fd);
    float* ph;   cudaGetSymbolAddress((void**)&ph,   g_h);
    float* px;   cudaGetSymbolAddress((void**)&px,   g_x);
    float* pgi;  cudaGetSymbolAddress((void**)&pgi,  g_gi);
    float* pgh;  cudaGetSymbolAddress((void**)&pgh,  g_gh);
    float* pmol; cudaGetSymbolAddress((void**)&pmol, g_mol);

    // init state
    copy_h_kernel<<<2048, 256>>>(h_nodes);
    copy_mol_kernel<<<(BATCH * H + 255) / 256, 256>>>(mol_feat);

    // CSR (static structure, rebuilt per launch; deterministic after sort)
    zero_indeg_kernel<<<(NN + 255) / 256, 256>>>();
    count_indeg_kernel<<<(EE + 255) / 256, 256>>>(dst);
    scan_kernel<<<1, 1024>>>();
    init_cursor_kernel<<<(NN + 255) / 256, 256>>>();
    scatter_kernel<<<(EE + 255) / 256, 256>>>(dst);
    sort_csr_kernel<<<(NN + 255) / 256, 256>>>();

    dim3 gemmGrid(HH / 128, NN / 128, 2);   // 48 x 49 x 2 (fs+fd fused)
    for (int t = 0; t < T_STEPS; t++) {
        const float* Wst = W_src + (size_t)t * H * HH;
        const float* Wdt = W_dst + (size_t)t * H * HH;
        const float* bst = b_src + (size_t)t * HH;
        const float* bdt = b_dst + (size_t)t * HH;
        const float* at  = attn_a + (size_t)t * HEADS * H;
        const float* Wiht = W_ih + (size_t)t * G3 * H;
        const float* Whht = W_hh + (size_t)t * G3 * H;
        const float* biht = b_ih + (size_t)t * G3;
        const float* bhht = b_hh + (size_t)t * G3;

        sgemm_dual<<<gemmGrid, 256>>>(ph, Wst, bst, Wdt, bdt, pfs, pfd, NN, HH, H);
        edge_logits_kernel<<<EE, 256>>>(src, dst, at);
        edge_softmax_kernel<<<(NN * HEADS + 255) / 256, 256>>>();
        aggregate_kernel<<<NN, 256>>>(src);
        gather_virtual_kernel<<<(BATCH * H + 255) / 256, 256>>>(vnids);
        gemm_nt16<<<dim3(G3 / 16, BATCH / 16), dim3(16, 16)>>>(px,   Wiht, biht, pgi, BATCH, G3, H);
        gemm_nt16<<<dim3(G3 / 16, BATCH / 16), dim3(16, 16)>>>(pmol, Whht, bhht, pgh, BATCH, G3, H);
        gru_gate_kernel<<<(BATCH * H + 255) / 256, 256>>>();
        attn_out_kernel<<<(BATCH * 48 + 255) / 256, 256>>>(attn_eids, out, t);
    }
    write_mol_out_kernel<<<(BATCH * H + 255) / 256, 256>>>(out);
}